// round 7
// baseline (speedup 1.0000x reference)
#include <cuda_runtime.h>
#include <cuda_bf16.h>

static constexpr int Bc      = 256;           // batches
static constexpr int Nn      = 512;           // nodes
static constexpr int SUBS    = 16;            // 32-row chunks per batch
static constexpr int SUBROWS = Nn / SUBS;     // 32 rows per work item
static constexpr int ITEMS   = Bc * SUBS;     // 4096 work items
static constexpr int NCTA    = 148 * 4;       // one full wave at 4 CTAs/SM
static constexpr int THREADS = 256;
static constexpr int WARPS   = THREADS / 32;  // 8 warps -> 4 rows/warp/item

// Deterministic partial sums [batch][sub] (no FP atomics anywhere)
__device__ float g_partial[Bc * SUBS];
// Per-batch completion counters (zero-init; self-reset every run)
__device__ int   g_count[Bc];

__global__ __launch_bounds__(THREADS, 4)
void gcn_persistent(const float* __restrict__ x,     // [B, N, 2]
                    const float* __restrict__ adj,   // [B, N, N]
                    const float* __restrict__ W1,    // [2, 4] row-major
                    const float* __restrict__ b1,    // [4]
                    const float* __restrict__ W2,    // [4, 1]
                    const float* __restrict__ b2,    // [1]
                    float* __restrict__ out)         // [B, 1]
{
    const int tid  = threadIdx.x;
    const int lane = tid & 31;
    const int warp = tid >> 5;

    __shared__ float sW[16];          // [0..7]=W1, [8..11]=b1, [12..15]=W2
    __shared__ float warp_sums[WARPS];
    if (tid < 8)  sW[tid]      = W1[tid];
    if (tid < 4)  sW[8 + tid]  = b1[tid];
    if (tid < 4)  sW[12 + tid] = W2[tid];
    __syncthreads();

    // Contiguous work partition: CTA i owns items [start, end)  (6 or 7 each)
    const int start = (int)(((long long)blockIdx.x       * ITEMS) / NCTA);
    const int end   = (int)(((long long)(blockIdx.x + 1) * ITEMS) / NCTA);

    // Per-lane fixed x-slice (cols m = it*128 + 4*lane + k), reloaded on batch change
    float rx0[16], rx1[16];
    int cur_b = -1;

    for (int w = start; w < end; ++w) {
        const int b   = w >> 4;           // / SUBS
        const int sub = w & (SUBS - 1);

        if (b != cur_b) {
            cur_b = b;
            const float* xb = x + (size_t)b * Nn * 2;
            #pragma unroll
            for (int it = 0; it < 4; ++it) {
                const int m = it * 128 + lane * 4;
                #pragma unroll
                for (int k = 0; k < 4; ++k) {
                    const float2 v = *(const float2*)(xb + (size_t)(m + k) * 2);
                    rx0[it * 4 + k] = v.x;
                    rx1[it * 4 + k] = v.y;
                }
            }
        }

        // Warp handles 4 contiguous rows of this 32-row chunk (2 x 2-row unroll)
        const int n0 = sub * SUBROWS + warp * 4;
        float wsum = 0.0f;

        #pragma unroll
        for (int rr = 0; rr < 4; rr += 2) {
            const float4* __restrict__ arow0 =
                (const float4*)(adj + ((size_t)b * Nn + n0 + rr) * Nn);
            const float4* __restrict__ arow1 = arow0 + (Nn / 4);

            float4 va[4], vb[4];
            #pragma unroll
            for (int it = 0; it < 4; ++it) va[it] = __ldcs(arow0 + it * 32 + lane);
            #pragma unroll
            for (int it = 0; it < 4; ++it) vb[it] = __ldcs(arow1 + it * 32 + lane);

            float s0a = 0.f, s1a = 0.f, s0b = 0.f, s1b = 0.f;
            #pragma unroll
            for (int it = 0; it < 4; ++it) {
                s0a = fmaf(va[it].x, rx0[it*4+0], s0a);  s1a = fmaf(va[it].x, rx1[it*4+0], s1a);
                s0a = fmaf(va[it].y, rx0[it*4+1], s0a);  s1a = fmaf(va[it].y, rx1[it*4+1], s1a);
                s0a = fmaf(va[it].z, rx0[it*4+2], s0a);  s1a = fmaf(va[it].z, rx1[it*4+2], s1a);
                s0a = fmaf(va[it].w, rx0[it*4+3], s0a);  s1a = fmaf(va[it].w, rx1[it*4+3], s1a);
                s0b = fmaf(vb[it].x, rx0[it*4+0], s0b);  s1b = fmaf(vb[it].x, rx1[it*4+0], s1b);
                s0b = fmaf(vb[it].y, rx0[it*4+1], s0b);  s1b = fmaf(vb[it].y, rx1[it*4+1], s1b);
                s0b = fmaf(vb[it].z, rx0[it*4+2], s0b);  s1b = fmaf(vb[it].z, rx1[it*4+2], s1b);
                s0b = fmaf(vb[it].w, rx0[it*4+3], s0b);  s1b = fmaf(vb[it].w, rx1[it*4+3], s1b);
            }

            #pragma unroll
            for (int off = 16; off > 0; off >>= 1) {
                s0a += __shfl_xor_sync(0xFFFFFFFFu, s0a, off);
                s1a += __shfl_xor_sync(0xFFFFFFFFu, s1a, off);
                s0b += __shfl_xor_sync(0xFFFFFFFFu, s0b, off);
                s1b += __shfl_xor_sync(0xFFFFFFFFu, s1b, off);
            }

            if (lane == 0) {
                float pa = 0.f, pb = 0.f;
                #pragma unroll
                for (int j = 0; j < 4; ++j) {
                    const float ha = fmaf(s0a, sW[j], fmaf(s1a, sW[4 + j], sW[8 + j]));
                    const float hb = fmaf(s0b, sW[j], fmaf(s1b, sW[4 + j], sW[8 + j]));
                    pa = fmaf(fmaxf(ha, 0.0f), sW[12 + j], pa);
                    pb = fmaf(fmaxf(hb, 0.0f), sW[12 + j], pb);
                }
                wsum += pa + pb;       // b2 added per-node in the finalizer
            }
        }

        if (lane == 0) warp_sums[warp] = wsum;
        __syncthreads();

        if (tid == 0) {
            float s = 0.0f;
            #pragma unroll
            for (int ww = 0; ww < WARPS; ++ww) s += warp_sums[ww];
            g_partial[b * SUBS + sub] = s;

            // last-chunk-finishes for this batch: int atomic only,
            // FP adds in fixed index order -> deterministic.
            __threadfence();
            const int old = atomicAdd(&g_count[b], 1);
            if (old == SUBS - 1) {
                float tot = (float)Nn * __ldcg(b2);
                #pragma unroll
                for (int k = 0; k < SUBS; ++k)
                    tot += __ldcg(&g_partial[b * SUBS + k]);
                out[b] = tot;
                g_count[b] = 0;        // reset for next graph replay
            }
        }
        __syncthreads();               // protect warp_sums reuse next item
    }
}

extern "C" void kernel_launch(void* const* d_in, const int* in_sizes, int n_in,
                              void* d_out, int out_size)
{
    const float* x   = (const float*)d_in[0];  // node_features [256,512,2]
    const float* adj = (const float*)d_in[1];  // adj_matrices  [256,512,512]
    const float* W1  = (const float*)d_in[2];  // [2,4]
    const float* b1  = (const float*)d_in[3];  // [4]
    const float* W2  = (const float*)d_in[4];  // [4,1]
    const float* b2  = (const float*)d_in[5];  // [1]
    float* out = (float*)d_out;                // [256,1]

    gcn_persistent<<<NCTA, THREADS>>>(x, adj, W1, b1, W2, b2, out);
}